// round 6
// baseline (speedup 1.0000x reference)
#include <cuda_runtime.h>
#include <cstdint>

// Problem dims (fixed by the dataset)
#define Bdim 128
#define Sdim 512
#define Idim 256
#define Hdim 1024
#define KTOT 1280           // Hdim + Idim
#define NCTA 128
#define NTHREADS 512
#define PITCH_W 1281        // odd pitch -> conflict-free two-row LDS broadcast
#define PITCH_A 130

typedef unsigned long long ull;

// Scratch (static device allocations are allowed; cudaMalloc is not)
__device__ float g_xT[(size_t)Sdim * Idim * Bdim];   // xT[t][i][b]
__device__ float g_hT[2][Hdim * Bdim];               // hT[buf][k][b]
__device__ unsigned g_sync[32];                      // barrier counter (memset per launch)

struct SmemLayout {
    float W[32][PITCH_W];    // rows lr = gate*8 + j : [W_hh | W_ih] combined, K=1280
    float acc[32][PITCH_A];  // gate pre-activations, 32 rows x 128 batch
    float c[8][Bdim];        // cell state for this CTA's 8 hidden units
    float bsum[32];          // b_ih + b_hh per owned row
    float red[16][10];       // output reduction scratch
};

__device__ __forceinline__ ull ffma2(ull a, ull b, ull c) {
    ull d;
    asm("fma.rn.f32x2 %0, %1, %2, %3;" : "=l"(d) : "l"(a), "l"(b), "l"(c));
    return d;
}
__device__ __forceinline__ ull pack2(float x) {
    ull d;
    asm("mov.b64 %0, {%1, %1};" : "=l"(d) : "f"(x));
    return d;
}
__device__ __forceinline__ ull add2(ull a, ull b) {
    ull d;
    asm("add.rn.f32x2 %0, %1, %2;" : "=l"(d) : "l"(a), "l"(b));
    return d;
}

__global__ void __launch_bounds__(NTHREADS, 1)
lstm_persistent(const float* __restrict__ x, const float* __restrict__ h0,
                const float* __restrict__ c0, const float* __restrict__ W_ih,
                const float* __restrict__ W_hh, const float* __restrict__ b_ih,
                const float* __restrict__ b_hh, const float* __restrict__ W_out,
                const float* __restrict__ b_out, float* __restrict__ out)
{
    extern __shared__ char smraw[];
    SmemLayout& sm = *reinterpret_cast<SmemLayout*>(smraw);
    const int tid = threadIdx.x;
    const int cta = blockIdx.x;
    const int u0  = cta * 8;     // first hidden unit owned by this CTA

    // ---- Prologue: stage weights into SMEM ------------------------------
    // lr = gate*8 + j  <->  global gate row r = gate*Hdim + u0 + j
    // NOTE: sm.W rows are only 4B-aligned (odd pitch) -> scalar STS, vector LDG.
    for (int idx = tid; idx < 32 * (Hdim / 4); idx += NTHREADS) {
        int lr  = idx >> 8;             // idx / 256
        int pos = (idx & 255) << 2;
        int r   = (lr >> 3) * Hdim + u0 + (lr & 7);
        float4 v = *reinterpret_cast<const float4*>(W_hh + (size_t)r * Hdim + pos);
        float* dst = &sm.W[lr][pos];
        dst[0] = v.x; dst[1] = v.y; dst[2] = v.z; dst[3] = v.w;
    }
    for (int idx = tid; idx < 32 * (Idim / 4); idx += NTHREADS) {
        int lr  = idx >> 6;             // idx / 64
        int pos = (idx & 63) << 2;
        int r   = (lr >> 3) * Hdim + u0 + (lr & 7);
        float4 v = *reinterpret_cast<const float4*>(W_ih + (size_t)r * Idim + pos);
        float* dst = &sm.W[lr][Hdim + pos];
        dst[0] = v.x; dst[1] = v.y; dst[2] = v.z; dst[3] = v.w;
    }
    if (tid < 32) {
        int r = (tid >> 3) * Hdim + u0 + (tid & 7);
        sm.bsum[tid] = b_ih[r] + b_hh[r];
    }
    for (int p = tid; p < 8 * Bdim; p += NTHREADS) {
        int u = p >> 7, b = p & 127;
        sm.c[u][b] = c0[(size_t)b * Hdim + u0 + u];
    }
    // hT[0] <- h0^T (grid-wide)
    for (int p = cta * NTHREADS + tid; p < Hdim * Bdim; p += NCTA * NTHREADS) {
        int k = p >> 7, b = p & 127;
        g_hT[0][p] = h0[(size_t)b * Hdim + k];
    }
    // xT[t][i][b] <- x[b][t][i]  (each CTA transposes 4 timesteps)
    for (int tt = 0; tt < 4; ++tt) {
        int t = cta * 4 + tt;
        float* dst = g_xT + (size_t)t * Idim * Bdim;
        const float* src = x + (size_t)t * Idim;
        for (int p = tid; p < Idim * Bdim; p += NTHREADS) {
            int i = p >> 7, b = p & 127;
            dst[p] = src[(size_t)b * Sdim * Idim + i];
        }
    }

    // ---- Software grid barrier (counter memset to 0 by host each launch) --
    int nbar = 0;
    auto gridbar = [&]() {
        __syncthreads();
        ++nbar;
        if (tid == 0) {
            __threadfence();
            atomicAdd(&g_sync[0], 1u);
            unsigned target = (unsigned)(NCTA * nbar);
            while (*((volatile unsigned*)&g_sync[0]) < target) __nanosleep(40);
            __threadfence();
        }
        __syncthreads();
    };

    gridbar();   // prologue scratch visible everywhere

    // ---- Recurrent loop --------------------------------------------------
    const int grp = tid >> 8;           // K-split group: 0 -> k[0,640), 1 -> k[640,1280)
    const int tl  = tid & 255;
    const int lr0 = (tl >> 4) << 1;     // 2 rows per thread
    const int b0  = (tl & 15) << 3;     // 8 batch cols per thread
    const float* Wr0 = sm.W[lr0];
    const float* Wr1 = sm.W[lr0 + 1];

    for (int t = 0; t < Sdim; ++t) {
        const float* hRead  = g_hT[t & 1];
        float*       hWrite = g_hT[(t + 1) & 1];

        ull a0 = 0, a1 = 0, a2 = 0, a3 = 0, a4 = 0, a5 = 0, a6 = 0, a7 = 0;

        auto gemm_accum = [&](const float* zbase, int wofs, int n) {
            #pragma unroll 4
            for (int kk = 0; kk < n; ++kk) {
                float w0 = Wr0[wofs + kk];
                float w1 = Wr1[wofs + kk];
                ull w0p = pack2(w0);
                ull w1p = pack2(w1);
                const ulonglong2* zp =
                    reinterpret_cast<const ulonglong2*>(zbase + kk * Bdim + b0);
                ulonglong2 za = zp[0];
                ulonglong2 zb = zp[1];
                a0 = ffma2(w0p, za.x, a0);
                a1 = ffma2(w0p, za.y, a1);
                a2 = ffma2(w0p, zb.x, a2);
                a3 = ffma2(w0p, zb.y, a3);
                a4 = ffma2(w1p, za.x, a4);
                a5 = ffma2(w1p, za.y, a5);
                a6 = ffma2(w1p, zb.x, a6);
                a7 = ffma2(w1p, zb.y, a7);
            }
        };

        if (grp == 0) {
            gemm_accum(hRead, 0, 640);                                   // k in [0,640)
        } else {
            gemm_accum(hRead + 640 * Bdim, 640, 384);                    // k in [640,1024)
            gemm_accum(g_xT + (size_t)t * Idim * Bdim, Hdim, 256);       // x part
        }

        // Merge the two K-halves through SMEM
        ull* accR0 = reinterpret_cast<ull*>(&sm.acc[lr0][b0]);
        ull* accR1 = reinterpret_cast<ull*>(&sm.acc[lr0 + 1][b0]);
        if (grp == 0) {
            accR0[0] = a0; accR0[1] = a1; accR0[2] = a2; accR0[3] = a3;
            accR1[0] = a4; accR1[1] = a5; accR1[2] = a6; accR1[3] = a7;
        }
        __syncthreads();
        if (grp == 1) {
            accR0[0] = add2(accR0[0], a0); accR0[1] = add2(accR0[1], a1);
            accR0[2] = add2(accR0[2], a2); accR0[3] = add2(accR0[3], a3);
            accR1[0] = add2(accR1[0], a4); accR1[1] = add2(accR1[1], a5);
            accR1[2] = add2(accR1[2], a6); accR1[3] = add2(accR1[3], a7);
        }
        __syncthreads();

        // Pointwise LSTM cell update for this CTA's 8 units x 128 batch
        #pragma unroll
        for (int rep = 0; rep < 2; ++rep) {
            int p = tid + rep * NTHREADS;
            int u = p >> 7, b = p & 127;
            float ipre = sm.acc[u][b]      + sm.bsum[u];
            float fpre = sm.acc[8  + u][b] + sm.bsum[8  + u];
            float gpre = sm.acc[16 + u][b] + sm.bsum[16 + u];
            float opre = sm.acc[24 + u][b] + sm.bsum[24 + u];
            float ig = 1.f / (1.f + expf(-ipre));
            float fg = 1.f / (1.f + expf(-fpre));
            float gg = tanhf(gpre);
            float og = 1.f / (1.f + expf(-opre));
            float cNew = fg * sm.c[u][b] + ig * gg;
            sm.c[u][b] = cNew;
            hWrite[(u0 + u) * Bdim + b] = og * tanhf(cNew);
        }

        gridbar();   // h(t+1) visible to all CTAs
    }

    // ---- Output: out[b] = h_last @ W_out^T + b_out  (CTA b = batch b) ----
    const float* hfin = g_hT[0];   // after 512 steps h lives in buffer 0
    float part[10];
    #pragma unroll
    for (int c_ = 0; c_ < 10; ++c_) part[c_] = 0.f;
    for (int k = tid; k < Hdim; k += NTHREADS) {
        float hv = hfin[k * Bdim + cta];
        #pragma unroll
        for (int c_ = 0; c_ < 10; ++c_)
            part[c_] += hv * W_out[c_ * Hdim + k];
    }
    int lane = tid & 31, wrp = tid >> 5;
    #pragma unroll
    for (int c_ = 0; c_ < 10; ++c_) {
        float v = part[c_];
        #pragma unroll
        for (int off = 16; off; off >>= 1)
            v += __shfl_down_sync(0xffffffffu, v, off);
        if (lane == 0) sm.red[wrp][c_] = v;
    }
    __syncthreads();
    if (tid < 10) {
        float s = b_out[tid];
        #pragma unroll
        for (int w = 0; w < 16; ++w) s += sm.red[w][tid];
        out[cta * 10 + tid] = s;
    }
}

extern "C" void kernel_launch(void* const* d_in, const int* in_sizes, int n_in,
                              void* d_out, int out_size)
{
    const float* x     = (const float*)d_in[0];
    const float* h0    = (const float*)d_in[1];
    const float* c0    = (const float*)d_in[2];
    const float* W_ih  = (const float*)d_in[3];
    const float* W_hh  = (const float*)d_in[4];
    const float* b_ih  = (const float*)d_in[5];
    const float* b_hh  = (const float*)d_in[6];
    const float* W_out = (const float*)d_in[7];
    const float* b_out = (const float*)d_in[8];
    float* out = (float*)d_out;

    // Reset the grid-barrier counter every launch (memset node is graph-capturable)
    void* syncPtr = nullptr;
    cudaGetSymbolAddress(&syncPtr, g_sync);
    cudaMemsetAsync(syncPtr, 0, sizeof(unsigned) * 32);

    int smem = (int)sizeof(SmemLayout);
    cudaFuncSetAttribute(lstm_persistent,
                         cudaFuncAttributeMaxDynamicSharedMemorySize, smem);
    lstm_persistent<<<NCTA, NTHREADS, smem>>>(x, h0, c0, W_ih, W_hh, b_ih, b_hh,
                                              W_out, b_out, out);
}

// round 9
// speedup vs baseline: 2.8053x; 2.8053x over previous
#include <cuda_runtime.h>
#include <cstdint>

// Problem dims (fixed by the dataset)
#define Bdim 128
#define Sdim 512
#define Idim 256
#define Hdim 1024
#define KTOT 1280
#define NCTA 128
#define NTHREADS 512
#define WT_PITCH 36          // floats per WT row: 144B, 16B-aligned, 4-bank rotation
#define PITCH_A 130

typedef unsigned long long ull;

// Scratch (static device allocations are allowed; cudaMalloc is not)
__device__ float g_xT[(size_t)Sdim * Idim * Bdim];   // xT[t][i][b]
__device__ float g_hT[2][Hdim * Bdim];               // hT[buf][k][b]
__device__ unsigned g_sync[32];                      // barrier counter (memset per launch)

struct SmemLayout {
    float WT[KTOT][WT_PITCH];  // transposed weights: WT[k][lr], lr = gate*8 + j
    float acc[32][PITCH_A];    // gate pre-activations, 32 rows x 128 batch
    float c[8][Bdim];          // cell state for this CTA's 8 hidden units
    float bsum[32];            // b_ih + b_hh per owned row
    float red[16][10];         // output reduction scratch
};
// sizeof ~ 205.8 KB < 227 KB

__device__ __forceinline__ ull ffma2(ull a, ull b, ull c) {
    ull d;
    asm("fma.rn.f32x2 %0, %1, %2, %3;" : "=l"(d) : "l"(a), "l"(b), "l"(c));
    return d;
}
__device__ __forceinline__ ull pack2(float x) {
    ull d;
    asm("mov.b64 %0, {%1, %1};" : "=l"(d) : "f"(x));
    return d;
}
__device__ __forceinline__ ull add2(ull a, ull b) {
    ull d;
    asm("add.rn.f32x2 %0, %1, %2;" : "=l"(d) : "l"(a), "l"(b));
    return d;
}

__global__ void __launch_bounds__(NTHREADS, 1)
lstm_persistent(const float* __restrict__ x, const float* __restrict__ h0,
                const float* __restrict__ c0, const float* __restrict__ W_ih,
                const float* __restrict__ W_hh, const float* __restrict__ b_ih,
                const float* __restrict__ b_hh, const float* __restrict__ W_out,
                const float* __restrict__ b_out, float* __restrict__ out)
{
    extern __shared__ char smraw[];
    SmemLayout& sm = *reinterpret_cast<SmemLayout*>(smraw);
    const int tid = threadIdx.x;
    const int cta = blockIdx.x;
    const int u0  = cta * 8;     // first hidden unit owned by this CTA

    // ---- Prologue: stage weights TRANSPOSED into SMEM: WT[k][lr] ---------
    for (int idx = tid; idx < 32 * (Hdim / 4); idx += NTHREADS) {
        int lr = idx >> 8;                 // 0..31
        int k4 = (idx & 255) << 2;         // 0..1020
        int r  = (lr >> 3) * Hdim + u0 + (lr & 7);
        float4 v = *reinterpret_cast<const float4*>(W_hh + (size_t)r * Hdim + k4);
        sm.WT[k4 + 0][lr] = v.x; sm.WT[k4 + 1][lr] = v.y;
        sm.WT[k4 + 2][lr] = v.z; sm.WT[k4 + 3][lr] = v.w;
    }
    for (int idx = tid; idx < 32 * (Idim / 4); idx += NTHREADS) {
        int lr = idx >> 6;                 // 0..31
        int k4 = (idx & 63) << 2;          // 0..252
        int r  = (lr >> 3) * Hdim + u0 + (lr & 7);
        float4 v = *reinterpret_cast<const float4*>(W_ih + (size_t)r * Idim + k4);
        sm.WT[Hdim + k4 + 0][lr] = v.x; sm.WT[Hdim + k4 + 1][lr] = v.y;
        sm.WT[Hdim + k4 + 2][lr] = v.z; sm.WT[Hdim + k4 + 3][lr] = v.w;
    }
    if (tid < 32) {
        int r = (tid >> 3) * Hdim + u0 + (tid & 7);
        sm.bsum[tid] = b_ih[r] + b_hh[r];
    }
    for (int p = tid; p < 8 * Bdim; p += NTHREADS) {
        int u = p >> 7, b = p & 127;
        sm.c[u][b] = c0[(size_t)b * Hdim + u0 + u];
    }
    // hT[0] <- h0^T (grid-wide)
    for (int p = cta * NTHREADS + tid; p < Hdim * Bdim; p += NCTA * NTHREADS) {
        int k = p >> 7, b = p & 127;
        g_hT[0][p] = h0[(size_t)b * Hdim + k];
    }
    // xT[t][i][b] <- x[b][t][i]  (each CTA transposes 4 timesteps)
    for (int tt = 0; tt < 4; ++tt) {
        int t = cta * 4 + tt;
        float* dst = g_xT + (size_t)t * Idim * Bdim;
        const float* src = x + (size_t)t * Idim;
        for (int p = tid; p < Idim * Bdim; p += NTHREADS) {
            int i = p >> 7, b = p & 127;
            dst[p] = src[(size_t)b * Sdim * Idim + i];
        }
    }

    // ---- Software grid barrier (counter memset to 0 by host each launch) --
    int nbar = 0;
    auto gridbar = [&]() {
        __syncthreads();
        ++nbar;
        if (tid == 0) {
            __threadfence();
            atomicAdd(&g_sync[0], 1u);
            unsigned target = (unsigned)(NCTA * nbar);
            while (*((volatile unsigned*)&g_sync[0]) < target) __nanosleep(40);
            __threadfence();
        }
        __syncthreads();
    };

    gridbar();   // prologue scratch visible everywhere

    // ---- Recurrent loop --------------------------------------------------
    // 8 K-groups x 64 threads. Thread tile: 8 gate rows x 8 batch cols.
    // Group g owns K-slice: h rows [128g,128g+128) + x rows [32g,32g+32).
    const int g   = tid >> 6;            // K-group 0..7
    const int loc = tid & 63;
    const int lr0 = (loc >> 4) * 8;      // 0,8,16,24
    const int b0  = (loc & 15) * 8;      // 0..120

    for (int t = 0; t < Sdim; ++t) {
        const float* hRead  = g_hT[t & 1];
        float*       hWrite = g_hT[(t + 1) & 1];

        ull acc[8][4];
        #pragma unroll
        for (int r = 0; r < 8; ++r)
            #pragma unroll
            for (int j = 0; j < 4; ++j) acc[r][j] = 0;

        auto gemm = [&](const float* zbase, int wcol0, int n) {
            const float* zp = zbase + b0;
            const float* wp = &sm.WT[wcol0][lr0];
            ulonglong2 cA = *reinterpret_cast<const ulonglong2*>(zp);
            ulonglong2 cB = *reinterpret_cast<const ulonglong2*>(zp + 4);
            for (int kk = 0; kk < n; ++kk) {
                // prefetch next z row (clamped on last iteration)
                const float* zn = zp + ((kk + 1 < n) ? Bdim : 0);
                ulonglong2 nA = *reinterpret_cast<const ulonglong2*>(zn);
                ulonglong2 nB = *reinterpret_cast<const ulonglong2*>(zn + 4);
                float4 wa = *reinterpret_cast<const float4*>(wp);
                float4 wb = *reinterpret_cast<const float4*>(wp + 4);
                float wf[8] = {wa.x, wa.y, wa.z, wa.w, wb.x, wb.y, wb.z, wb.w};
                ull wd[8];
                #pragma unroll
                for (int r = 0; r < 8; ++r) wd[r] = pack2(wf[r]);
                #pragma unroll
                for (int r = 0; r < 8; ++r) {
                    acc[r][0] = ffma2(wd[r], cA.x, acc[r][0]);
                    acc[r][1] = ffma2(wd[r], cA.y, acc[r][1]);
                    acc[r][2] = ffma2(wd[r], cB.x, acc[r][2]);
                    acc[r][3] = ffma2(wd[r], cB.y, acc[r][3]);
                }
                zp += Bdim; wp += WT_PITCH;
                cA = nA; cB = nB;
            }
        };

        gemm(hRead + 128 * g * Bdim, 128 * g, 128);                         // h slice
        gemm(g_xT + (size_t)t * Idim * Bdim + 32 * g * Bdim,
             Hdim + 32 * g, 32);                                            // x slice

        // ---- 8-way merge through SMEM (sequential passes) ----
        #pragma unroll 1
        for (int pass = 0; pass < 8; ++pass) {
            if (g == pass) {
                #pragma unroll
                for (int r = 0; r < 8; ++r) {
                    ull* dst = reinterpret_cast<ull*>(&sm.acc[lr0 + r][b0]);
                    if (pass == 0) {
                        dst[0] = acc[r][0]; dst[1] = acc[r][1];
                        dst[2] = acc[r][2]; dst[3] = acc[r][3];
                    } else {
                        dst[0] = add2(dst[0], acc[r][0]);
                        dst[1] = add2(dst[1], acc[r][1]);
                        dst[2] = add2(dst[2], acc[r][2]);
                        dst[3] = add2(dst[3], acc[r][3]);
                    }
                }
            }
            __syncthreads();
        }

        // Pointwise LSTM cell update for this CTA's 8 units x 128 batch
        #pragma unroll
        for (int rep = 0; rep < 2; ++rep) {
            int p = tid + rep * NTHREADS;
            int u = p >> 7, b = p & 127;
            float ipre = sm.acc[u][b]      + sm.bsum[u];
            float fpre = sm.acc[8  + u][b] + sm.bsum[8  + u];
            float gpre = sm.acc[16 + u][b] + sm.bsum[16 + u];
            float opre = sm.acc[24 + u][b] + sm.bsum[24 + u];
            float ig = 1.f / (1.f + expf(-ipre));
            float fg = 1.f / (1.f + expf(-fpre));
            float gg = tanhf(gpre);
            float og = 1.f / (1.f + expf(-opre));
            float cNew = fg * sm.c[u][b] + ig * gg;
            sm.c[u][b] = cNew;
            hWrite[(u0 + u) * Bdim + b] = og * tanhf(cNew);
        }

        gridbar();   // h(t+1) visible to all CTAs
    }

    // ---- Output: out[b] = h_last @ W_out^T + b_out  (CTA b = batch b) ----
    const float* hfin = g_hT[0];   // after 512 steps h lives in buffer 0
    float part[10];
    #pragma unroll
    for (int c_ = 0; c_ < 10; ++c_) part[c_] = 0.f;
    for (int k = tid; k < Hdim; k += NTHREADS) {
        float hv = hfin[k * Bdim + cta];
        #pragma unroll
        for (int c_ = 0; c_ < 10; ++c_)
            part[c_] += hv * W_out[c_ * Hdim + k];
    }
    int lane = tid & 31, wrp = tid >> 5;
    #pragma unroll
    for (int c_ = 0; c_ < 10; ++c_) {
        float v = part[c_];
        #pragma unroll
        for (int off = 16; off; off >>= 1)
            v += __shfl_down_sync(0xffffffffu, v, off);
        if (lane == 0) sm.red[wrp][c_] = v;
    }
    __syncthreads();
    if (tid < 10) {
        float s = b_out[tid];
        #pragma unroll
        for (int w = 0; w < 16; ++w) s += sm.red[w][tid];
        out[cta * 10 + tid] = s;
    }
}

extern "C" void kernel_launch(void* const* d_in, const int* in_sizes, int n_in,
                              void* d_out, int out_size)
{
    const float* x     = (const float*)d_in[0];
    const float* h0    = (const float*)d_in[1];
    const float* c0    = (const float*)d_in[2];
    const float* W_ih  = (const float*)d_in[3];
    const float* W_hh  = (const float*)d_in[4];
    const float* b_ih  = (const float*)d_in[5];
    const float* b_hh  = (const float*)d_in[6];
    const float* W_out = (const float*)d_in[7];
    const float* b_out = (const float*)d_in[8];
    float* out = (float*)d_out;

    // Reset the grid-barrier counter every launch (memset node is graph-capturable)
    void* syncPtr = nullptr;
    cudaGetSymbolAddress(&syncPtr, g_sync);
    cudaMemsetAsync(syncPtr, 0, sizeof(unsigned) * 32);

    int smem = (int)sizeof(SmemLayout);
    cudaFuncSetAttribute(lstm_persistent,
                         cudaFuncAttributeMaxDynamicSharedMemorySize, smem);
    lstm_persistent<<<NCTA, NTHREADS, smem>>>(x, h0, c0, W_ih, W_hh, b_ih, b_hh,
                                              W_out, b_out, out);
}